// round 6
// baseline (speedup 1.0000x reference)
#include <cuda_runtime.h>

#define NN 2048
#define FEAT 64
#define HID 16
#define C 8
#define NG 64
#define RPT 32                 // rows per warp task (== warp size, for shfl broadcast)
#define PF 16                  // prefetch depth (MLP)

// scratch (allocation-free rule: device globals)
__device__ __align__(16) float g_node[NN * C];   // 64 KB, per-node summed feature MLP
__device__ __align__(16) float e_tab[11 * C];    // rho-MLP table for dist = 0..10

// ---------------------------------------------------------------------------
// Kernel 1: g[n,c] = sum_f ( sum_h relu(x[n,f]*w1[f,h]+b1[f,h]) * w2[f,h,c] + b2[f,c] )
// Block = 256 threads = 4 nodes x 64 features. Grid = 512.
// Block 0 additionally builds the e-table and zeroes d_out.
// ---------------------------------------------------------------------------
__global__ void __launch_bounds__(256) tgnan_k1(
    const float* __restrict__ x,
    const float* __restrict__ w1, const float* __restrict__ b1,
    const float* __restrict__ w2, const float* __restrict__ b2,
    const float* __restrict__ rw1, const float* __restrict__ rb1,
    const float* __restrict__ rw2, const float* __restrict__ rb2,
    float* __restrict__ out)
{
    const int nsub = threadIdx.x >> 6;            // 0..3
    const int f    = threadIdx.x & 63;            // 0..63
    const int n    = blockIdx.x * 4 + nsub;

    const float xv = __ldg(x + n * FEAT + f);
    float acc[C];
#pragma unroll
    for (int c = 0; c < C; c++) acc[c] = __ldg(b2 + f * C + c);

#pragma unroll
    for (int h = 0; h < HID; h++) {
        const float hv = fmaxf(fmaf(xv, __ldg(w1 + f * HID + h), __ldg(b1 + f * HID + h)), 0.0f);
        const float4* wp = reinterpret_cast<const float4*>(w2 + (size_t)(f * HID + h) * C);
        const float4 wa = __ldg(wp);
        const float4 wb = __ldg(wp + 1);
        acc[0] = fmaf(hv, wa.x, acc[0]);
        acc[1] = fmaf(hv, wa.y, acc[1]);
        acc[2] = fmaf(hv, wa.z, acc[2]);
        acc[3] = fmaf(hv, wa.w, acc[3]);
        acc[4] = fmaf(hv, wb.x, acc[4]);
        acc[5] = fmaf(hv, wb.y, acc[5]);
        acc[6] = fmaf(hv, wb.z, acc[6]);
        acc[7] = fmaf(hv, wb.w, acc[7]);
    }

    // reduce over 64 features: butterfly within warp, cross-warp via smem
#pragma unroll
    for (int off = 16; off; off >>= 1)
#pragma unroll
        for (int c = 0; c < C; c++)
            acc[c] += __shfl_xor_sync(0xffffffffu, acc[c], off);

    __shared__ float red[4][2][C];
    if ((f & 31) == 0) {
#pragma unroll
        for (int c = 0; c < C; c++) red[nsub][f >> 5][c] = acc[c];
    }
    __syncthreads();
    if (f < C) g_node[n * C + f] = red[nsub][0][f] + red[nsub][1][f];

    if (blockIdx.x == 0) {
        const int tid = threadIdx.x;
        // e-table: rho MLP at dist = 0..10 (dist = -1 contributes 0)
        if (tid < 11) {
            const float dd = (float)tid;
            float a2[C];
#pragma unroll
            for (int c = 0; c < C; c++) a2[c] = rb2[c];
#pragma unroll
            for (int h = 0; h < HID; h++) {
                const float hv = fmaxf(fmaf(dd, rw1[h], rb1[h]), 0.0f);
#pragma unroll
                for (int c = 0; c < C; c++)
                    a2[c] = fmaf(hv, rw2[h * C + c], a2[c]);
            }
#pragma unroll
            for (int c = 0; c < C; c++) e_tab[tid * C + c] = a2[c];
        }
        // zero output (d_out is poisoned; k2 accumulates atomically)
        for (int i = tid; i < NG * C; i += 256) out[i] = 0.0f;
    }
}

// ---------------------------------------------------------------------------
// Kernel 2: out[b,c] += sum_m g[m,c] * sum_{n in b} e[dist(n,m), c]
// Warp task = 32 consecutive m (lane = m) x 32 consecutive rows n.
// Histogram of dist values in 2x u64 (12 buckets x 10-bit fields, max 32 per
// field) flushed ONLY at graph boundaries + task end. Prefetch depth 16.
// ---------------------------------------------------------------------------
__global__ void __launch_bounds__(128) tgnan_k2(
    const float* __restrict__ dist,
    const int* __restrict__ batch,
    float* __restrict__ out)
{
    __shared__ float er_s[11][C];
    {   // stage e-table once per block
        const int t = threadIdx.x;
        if (t < 11 * C) ((float*)er_s)[t] = e_tab[t];
    }
    __syncthreads();

    const int w    = (blockIdx.x * 128 + threadIdx.x) >> 5;  // 0..4095
    const int lane = threadIdx.x & 31;
    const int mc   = w & 63;          // m-chunk (4 consecutive per block -> 512B/row)
    const int rb   = w >> 6;          // row-block
    const int m    = mc * 32 + lane;
    const int r0   = rb * RPT;

    // g row for this lane's m (constant across the task)
    float gv[C];
    {
        const float4* gp = reinterpret_cast<const float4*>(g_node + (size_t)m * C);
        const float4 ga = gp[0];
        const float4 gb4 = gp[1];
        gv[0] = ga.x; gv[1] = ga.y; gv[2] = ga.z; gv[3] = ga.w;
        gv[4] = gb4.x; gv[5] = gb4.y; gv[6] = gb4.z; gv[7] = gb4.w;
    }

    // graph id per row, one per lane, broadcast via shfl
    const int bid = __ldg(batch + r0 + lane);

    unsigned long long h0 = 0ull, h1 = 0ull;   // buckets 0..5 / 6..11, 10-bit fields
    int cur_g = __shfl_sync(0xffffffffu, bid, 0);

    const float* pd = dist + (size_t)r0 * NN + m;

    auto emit = [&]() {
        float p[C];
#pragma unroll
        for (int c = 0; c < C; c++) p[c] = 0.0f;
#pragma unroll
        for (int d = 1; d < 12; d++) {           // bucket 0 == dist -1 -> contributes 0
            const unsigned int cnt = (unsigned int)
                ((d < 6 ? (h0 >> (10 * d)) : (h1 >> (10 * (d - 6)))) & 1023u);
            const float fc = (float)cnt;
#pragma unroll
            for (int c = 0; c < C; c++)
                p[c] = fmaf(fc, er_s[d - 1][c], p[c]);
        }
#pragma unroll
        for (int c = 0; c < C; c++) p[c] *= gv[c];
#pragma unroll
        for (int off = 16; off; off >>= 1)
#pragma unroll
            for (int c = 0; c < C; c++)
                p[c] += __shfl_xor_sync(0xffffffffu, p[c], off);
        if (lane == 0) {
#pragma unroll
            for (int c = 0; c < C; c++) atomicAdd(out + cur_g * C + c, p[c]);
        }
        h0 = 0ull; h1 = 0ull;
    };

#pragma unroll
    for (int n0 = 0; n0 < RPT; n0 += PF) {
        // unconditional batched prefetch: 16 independent LDGs in flight
        float fd[PF];
#pragma unroll
        for (int i = 0; i < PF; i++)
            fd[i] = __ldg(pd + (size_t)(n0 + i) * NN);

#pragma unroll
        for (int i = 0; i < PF; i++) {
            const int gid = __shfl_sync(0xffffffffu, bid, n0 + i);  // warp-uniform
            if (gid != cur_g) {                  // rare (~1 per task)
                emit();
                cur_g = gid;
            }
            int di = (int)fd[i] + 1;             // -1..10 -> 0..11
            di = max(0, min(11, di));            // safety clamp
            const int sel = di >= 6;
            const unsigned long long inc = 1ull << (10 * (di - 6 * sel));
            if (sel) h1 += inc; else h0 += inc;
        }
    }
    emit();
}

// ---------------------------------------------------------------------------
extern "C" void kernel_launch(void* const* d_in, const int* in_sizes, int n_in,
                              void* d_out, int out_size)
{
    const float* x    = (const float*)d_in[0];
    const float* dist = (const float*)d_in[1];
    const int*   bv   = (const int*)d_in[2];
    const float* fw1  = (const float*)d_in[3];
    const float* fb1  = (const float*)d_in[4];
    const float* fw2  = (const float*)d_in[5];
    const float* fb2  = (const float*)d_in[6];
    const float* rw1  = (const float*)d_in[7];
    const float* rb1  = (const float*)d_in[8];
    const float* rw2  = (const float*)d_in[9];
    const float* rb2  = (const float*)d_in[10];
    float* out = (float*)d_out;

    tgnan_k1<<<512, 256>>>(x, fw1, fb1, fw2, fb2, rw1, rb1, rw2, rb2, out);
    tgnan_k2<<<1024, 128>>>(dist, bv, out);
}

// round 7
// speedup vs baseline: 1.2950x; 1.2950x over previous
#include <cuda_runtime.h>

#define NN 2048
#define FEAT 64
#define HID 16
#define C 8
#define NG 64
#define MAXSEG 128     // hard bound: sum ceil(len_g/32) <= 64 + 64

// scratch (allocation-free rule: device globals)
__device__ __align__(16) float g_node[NN * C];   // per-node summed feature MLP
__device__ __align__(16) float e_tab[11 * C];    // rho-MLP table for dist = 0..10
__device__ int d_seg_start[MAXSEG];
__device__ int d_seg_len[MAXSEG];
__device__ int d_seg_graph[MAXSEG];
__device__ int d_nseg;

// ---------------------------------------------------------------------------
// Kernel 0: build graph-aligned segments of <=32 contiguous rows.
// 64 threads, one per graph: binary-search row range, warp-scan slot offsets.
// ---------------------------------------------------------------------------
__global__ void __launch_bounds__(64) tgnan_k0(const int* __restrict__ batch)
{
    const int g    = threadIdx.x;          // 0..63
    const int lane = g & 31;
    const int warp = g >> 5;

    // lower_bound(batch, g) and lower_bound(batch, g+1)
    int lo = 0, hi = NN;
    while (lo < hi) { int mid = (lo + hi) >> 1; if (batch[mid] < g) lo = mid + 1; else hi = mid; }
    const int start = lo;
    int lo2 = lo, hi2 = NN;
    while (lo2 < hi2) { int mid = (lo2 + hi2) >> 1; if (batch[mid] < g + 1) lo2 = mid + 1; else hi2 = mid; }
    const int len = lo2 - start;
    const int ns  = (len + 31) >> 5;       // segments this graph owns (0 if empty)

    // exclusive prefix sum of ns over 64 threads
    int v = ns;
#pragma unroll
    for (int o = 1; o < 32; o <<= 1) {
        int t = __shfl_up_sync(0xffffffffu, v, o);
        if (lane >= o) v += t;
    }
    __shared__ int wsum;
    if (warp == 0 && lane == 31) wsum = v;
    __syncthreads();
    const int off = v - ns + (warp ? wsum : 0);

    for (int i = 0; i < ns; i++) {
        d_seg_start[off + i] = start + i * 32;
        d_seg_len[off + i]   = min(32, len - i * 32);
        d_seg_graph[off + i] = g;
    }
    if (g == 63) d_nseg = off + ns;
}

// ---------------------------------------------------------------------------
// Kernel 1: g[n,c] = sum_f ( sum_h relu(x[n,f]*w1[f,h]+b1[f,h]) * w2[f,h,c] + b2[f,c] )
// Block = 64 threads (one per feature), grid = 2048 (one per node).
// Block 0 additionally builds the e-table and zeroes d_out.
// ---------------------------------------------------------------------------
__global__ void __launch_bounds__(FEAT) tgnan_k1(
    const float* __restrict__ x,
    const float* __restrict__ w1, const float* __restrict__ b1,
    const float* __restrict__ w2, const float* __restrict__ b2,
    const float* __restrict__ rw1, const float* __restrict__ rb1,
    const float* __restrict__ rw2, const float* __restrict__ rb2,
    float* __restrict__ out)
{
    const int n = blockIdx.x;
    const int f = threadIdx.x;           // 0..63

    const float xv = x[n * FEAT + f];
    float acc[C];
#pragma unroll
    for (int c = 0; c < C; c++) acc[c] = b2[f * C + c];

#pragma unroll
    for (int h = 0; h < HID; h++) {
        const float hv = fmaxf(fmaf(xv, w1[f * HID + h], b1[f * HID + h]), 0.0f);
        const float4* wp = reinterpret_cast<const float4*>(w2 + (size_t)(f * HID + h) * C);
        const float4 wa = __ldg(wp);
        const float4 wb = __ldg(wp + 1);
        acc[0] = fmaf(hv, wa.x, acc[0]);
        acc[1] = fmaf(hv, wa.y, acc[1]);
        acc[2] = fmaf(hv, wa.z, acc[2]);
        acc[3] = fmaf(hv, wa.w, acc[3]);
        acc[4] = fmaf(hv, wb.x, acc[4]);
        acc[5] = fmaf(hv, wb.y, acc[5]);
        acc[6] = fmaf(hv, wb.z, acc[6]);
        acc[7] = fmaf(hv, wb.w, acc[7]);
    }

#pragma unroll
    for (int off = 16; off; off >>= 1)
#pragma unroll
        for (int c = 0; c < C; c++)
            acc[c] += __shfl_xor_sync(0xffffffffu, acc[c], off);

    __shared__ float red[2][C];
    if ((f & 31) == 0) {
#pragma unroll
        for (int c = 0; c < C; c++) red[f >> 5][c] = acc[c];
    }
    __syncthreads();
    if (f < C) g_node[n * C + f] = red[0][f] + red[1][f];

    if (n == 0) {
        if (f < 11) {
            const float dd = (float)f;
            float a2[C];
#pragma unroll
            for (int c = 0; c < C; c++) a2[c] = rb2[c];
#pragma unroll
            for (int h = 0; h < HID; h++) {
                const float hv = fmaxf(fmaf(dd, rw1[h], rb1[h]), 0.0f);
#pragma unroll
                for (int c = 0; c < C; c++)
                    a2[c] = fmaf(hv, rw2[h * C + c], a2[c]);
            }
#pragma unroll
            for (int c = 0; c < C; c++) e_tab[f * C + c] = a2[c];
        }
        for (int i = f; i < NG * C; i += FEAT) out[i] = 0.0f;
    }
}

// ---------------------------------------------------------------------------
// Kernel 2: out[b,c] += sum_m g[m,c] * sum_{n in segment} e[dist(n,m), c]
// Block = 256 thr = 8 warps. blockIdx.x = m-group (8 warps x 32 cols = 256 m),
// blockIdx.y = segment. Hot loop: 32 predicated LDGs (padding -> dist=-1 ->
// bucket 0 -> contributes 0), batched 16 deep; 12x10-bit 2xu64 histogram.
// Emit once per task; block-level reduce -> 8 atomics per block.
// ---------------------------------------------------------------------------
__global__ void __launch_bounds__(256) tgnan_k2(
    const float* __restrict__ dist,
    float* __restrict__ out)
{
    __shared__ float er_s[11][C];
    __shared__ float bp[8][C];
    if (threadIdx.x < 11 * C) ((float*)er_s)[threadIdx.x] = e_tab[threadIdx.x];
    __syncthreads();

    const int seg = blockIdx.y;
    if (seg >= d_nseg) return;               // block-uniform exit

    const int wid  = threadIdx.x >> 5;       // 0..7
    const int lane = threadIdx.x & 31;
    const int m    = (blockIdx.x * 8 + wid) * 32 + lane;
    const int start = d_seg_start[seg];
    const int len   = d_seg_len[seg];
    const int gb    = d_seg_graph[seg];

    const float* pd = dist + (size_t)start * NN + m;

    unsigned long long h0 = 0ull, h1 = 0ull; // buckets 0..5 / 6..11, 10-bit fields
#pragma unroll
    for (int half = 0; half < 2; half++) {
        float fd[16];
#pragma unroll
        for (int i = 0; i < 16; i++) {       // 16 independent predicated LDGs
            const int r = half * 16 + i;
            fd[i] = (r < len) ? __ldg(pd + (size_t)r * NN) : -1.0f;
        }
#pragma unroll
        for (int i = 0; i < 16; i++) {
            int di = (int)fd[i] + 1;         // -1..10 -> 0..11 (exact ints)
            di = max(0, min(11, di));
            const bool hi = di >= 6;
            const unsigned long long inc = 1ull << (10 * (hi ? di - 6 : di));
            if (hi) h1 += inc; else h0 += inc;
        }
    }

    // emit: p[c] = (sum_d cnt_d * e[d,c]) * g[m,c]
    float p[C];
#pragma unroll
    for (int c = 0; c < C; c++) p[c] = 0.0f;
#pragma unroll
    for (int d = 1; d < 12; d++) {           // bucket 0 (dist=-1) contributes 0
        const unsigned int cnt = (unsigned int)
            ((d < 6 ? (h0 >> (10 * d)) : (h1 >> (10 * (d - 6)))) & 1023u);
        const float fc = (float)cnt;
#pragma unroll
        for (int c = 0; c < C; c++)
            p[c] = fmaf(fc, er_s[d - 1][c], p[c]);
    }
    {
        const float4* gp = reinterpret_cast<const float4*>(g_node + (size_t)m * C);
        const float4 ga = gp[0];
        const float4 gb4 = gp[1];
        p[0] *= ga.x;  p[1] *= ga.y;  p[2] *= ga.z;  p[3] *= ga.w;
        p[4] *= gb4.x; p[5] *= gb4.y; p[6] *= gb4.z; p[7] *= gb4.w;
    }
#pragma unroll
    for (int off = 16; off; off >>= 1)
#pragma unroll
        for (int c = 0; c < C; c++)
            p[c] += __shfl_xor_sync(0xffffffffu, p[c], off);

    if (lane == 0) {
#pragma unroll
        for (int c = 0; c < C; c++) bp[wid][c] = p[c];
    }
    __syncthreads();
    if (threadIdx.x < C) {
        float s = 0.0f;
#pragma unroll
        for (int ww = 0; ww < 8; ww++) s += bp[ww][threadIdx.x];
        atomicAdd(out + gb * C + threadIdx.x, s);
    }
}

// ---------------------------------------------------------------------------
extern "C" void kernel_launch(void* const* d_in, const int* in_sizes, int n_in,
                              void* d_out, int out_size)
{
    const float* x    = (const float*)d_in[0];
    const float* dist = (const float*)d_in[1];
    const int*   bv   = (const int*)d_in[2];
    const float* fw1  = (const float*)d_in[3];
    const float* fb1  = (const float*)d_in[4];
    const float* fw2  = (const float*)d_in[5];
    const float* fb2  = (const float*)d_in[6];
    const float* rw1  = (const float*)d_in[7];
    const float* rb1  = (const float*)d_in[8];
    const float* rw2  = (const float*)d_in[9];
    const float* rb2  = (const float*)d_in[10];
    float* out = (float*)d_out;

    tgnan_k0<<<1, 64>>>(bv);
    tgnan_k1<<<NN, FEAT>>>(x, fw1, fb1, fw2, fb2, rw1, rb1, rw2, rb2, out);
    dim3 g2(8, MAXSEG, 1);                   // 8 m-groups x up to 128 segments
    tgnan_k2<<<g2, 256>>>(dist, out);
}

// round 8
// speedup vs baseline: 1.3768x; 1.0632x over previous
#include <cuda_runtime.h>

#define NN 2048
#define FEAT 64
#define HID 16
#define C 8
#define NG 64
#define MAXSEG 128     // hard bound: sum ceil(len_g/32) <= 64 + 64

// scratch (allocation-free rule: device globals)
__device__ __align__(16) float g_node[NN * C];   // per-node summed feature MLP
__device__ __align__(16) float e_tab[11 * C];    // rho-MLP table for dist = 0..10
__device__ int d_seg_start[MAXSEG];
__device__ int d_seg_len[MAXSEG];
__device__ int d_seg_graph[MAXSEG];
__device__ int d_nseg;

// ---------------------------------------------------------------------------
// Kernel 1: g[n,c] = sum_f ( sum_h relu(x[n,f]*w1[f,h]+b1[f,h]) * w2[f,h,c] + b2[f,c] )
// Block = 64 threads (one per feature), grid = 2048 (one per node).
// Block 0 additionally: e-table, d_out zeroing, and PARALLEL segment build
// (replaces the old 9.6us binary-search kernel).
// ---------------------------------------------------------------------------
__global__ void __launch_bounds__(FEAT) tgnan_k1(
    const float* __restrict__ x,
    const int*   __restrict__ batch,
    const float* __restrict__ w1, const float* __restrict__ b1,
    const float* __restrict__ w2, const float* __restrict__ b2,
    const float* __restrict__ rw1, const float* __restrict__ rb1,
    const float* __restrict__ rw2, const float* __restrict__ rb2,
    float* __restrict__ out)
{
    const int n = blockIdx.x;
    const int f = threadIdx.x;           // 0..63

    const float xv = x[n * FEAT + f];
    float acc[C];
#pragma unroll
    for (int c = 0; c < C; c++) acc[c] = b2[f * C + c];

#pragma unroll
    for (int h = 0; h < HID; h++) {
        const float hv = fmaxf(fmaf(xv, w1[f * HID + h], b1[f * HID + h]), 0.0f);
        const float4* wp = reinterpret_cast<const float4*>(w2 + (size_t)(f * HID + h) * C);
        const float4 wa = __ldg(wp);
        const float4 wb = __ldg(wp + 1);
        acc[0] = fmaf(hv, wa.x, acc[0]);
        acc[1] = fmaf(hv, wa.y, acc[1]);
        acc[2] = fmaf(hv, wa.z, acc[2]);
        acc[3] = fmaf(hv, wa.w, acc[3]);
        acc[4] = fmaf(hv, wb.x, acc[4]);
        acc[5] = fmaf(hv, wb.y, acc[5]);
        acc[6] = fmaf(hv, wb.z, acc[6]);
        acc[7] = fmaf(hv, wb.w, acc[7]);
    }

#pragma unroll
    for (int off = 16; off; off >>= 1)
#pragma unroll
        for (int c = 0; c < C; c++)
            acc[c] += __shfl_xor_sync(0xffffffffu, acc[c], off);

    __shared__ float red[2][C];
    if ((f & 31) == 0) {
#pragma unroll
        for (int c = 0; c < C; c++) red[f >> 5][c] = acc[c];
    }
    __syncthreads();
    if (f < C) g_node[n * C + f] = red[0][f] + red[1][f];

    if (n == 0) {
        // ---- e-table: rho MLP at dist = 0..10 (dist = -1 contributes 0) ----
        if (f < 11) {
            const float dd = (float)f;
            float a2[C];
#pragma unroll
            for (int c = 0; c < C; c++) a2[c] = rb2[c];
#pragma unroll
            for (int h = 0; h < HID; h++) {
                const float hv = fmaxf(fmaf(dd, rw1[h], rb1[h]), 0.0f);
#pragma unroll
                for (int c = 0; c < C; c++)
                    a2[c] = fmaf(hv, rw2[h * C + c], a2[c]);
            }
#pragma unroll
            for (int c = 0; c < C; c++) e_tab[f * C + c] = a2[c];
        }
        // ---- zero output (d_out is poisoned; k2 accumulates atomically) ----
        for (int i = f; i < NG * C; i += FEAT) out[i] = 0.0f;

        // ---- parallel segment build (order-independent slot allocation) ----
        __shared__ int bstart[NG + 1];
        __shared__ int nseg_s;
        bstart[f] = -1;
        if (f == 0) { bstart[NG] = NN; nseg_s = 0; }
        __syncthreads();
        // each thread scans 32 rows; first row of each graph -> bstart[g]=r
        {
            const int r0 = f * 32;
            int prev = (r0 == 0) ? -1 : __ldg(batch + r0 - 1);
            for (int i = 0; i < 32; i++) {
                const int b = __ldg(batch + r0 + i);
                if (b != prev) bstart[b] = r0 + i;   // unique writer per graph
                prev = b;
            }
        }
        __syncthreads();
        // thread f = graph f: emit its <=ceil(len/32) segments
        {
            const int s = bstart[f];
            if (s >= 0) {
                int e = NN;
                for (int g2 = f + 1; g2 <= NG; g2++) {
                    if (bstart[g2] >= 0) { e = bstart[g2]; break; }
                }
                const int len = e - s;
                const int ns  = (len + 31) >> 5;
                const int off = atomicAdd(&nseg_s, ns);
                for (int i = 0; i < ns; i++) {
                    d_seg_start[off + i] = s + i * 32;
                    d_seg_len[off + i]   = min(32, len - i * 32);
                    d_seg_graph[off + i] = f;
                }
            }
        }
        __syncthreads();
        if (f == 0) d_nseg = nseg_s;
    }
}

// ---------------------------------------------------------------------------
// Kernel 2: out[b,c] += sum_m g[m,c] * sum_{n in segment} e[dist(n,m), c]
// Block = 256 thr = 8 warps. blockIdx.x = m-group (8 warps x 32 cols = 256 m),
// blockIdx.y = segment. Hot loop: 32 predicated LDGs (padding -> dist=-1 ->
// bucket 0 -> contributes 0), batched 16 deep; 12x10-bit 2xu64 histogram.
// Emit once per task; block-level reduce -> 8 atomics per block.
// ---------------------------------------------------------------------------
__global__ void __launch_bounds__(256) tgnan_k2(
    const float* __restrict__ dist,
    float* __restrict__ out)
{
    __shared__ float er_s[11][C];
    __shared__ float bp[8][C];
    if (threadIdx.x < 11 * C) ((float*)er_s)[threadIdx.x] = e_tab[threadIdx.x];
    __syncthreads();

    const int seg = blockIdx.y;
    if (seg >= d_nseg) return;               // block-uniform exit

    const int wid  = threadIdx.x >> 5;       // 0..7
    const int lane = threadIdx.x & 31;
    const int m    = (blockIdx.x * 8 + wid) * 32 + lane;
    const int start = d_seg_start[seg];
    const int len   = d_seg_len[seg];
    const int gb    = d_seg_graph[seg];

    const float* pd = dist + (size_t)start * NN + m;

    unsigned long long h0 = 0ull, h1 = 0ull; // buckets 0..5 / 6..11, 10-bit fields
#pragma unroll
    for (int half = 0; half < 2; half++) {
        float fd[16];
#pragma unroll
        for (int i = 0; i < 16; i++) {       // 16 independent predicated LDGs
            const int r = half * 16 + i;
            fd[i] = (r < len) ? __ldg(pd + (size_t)r * NN) : -1.0f;
        }
#pragma unroll
        for (int i = 0; i < 16; i++) {
            int di = (int)fd[i] + 1;         // -1..10 -> 0..11 (exact ints)
            di = max(0, min(11, di));
            const bool hi = di >= 6;
            const unsigned long long inc = 1ull << (10 * (hi ? di - 6 : di));
            if (hi) h1 += inc; else h0 += inc;
        }
    }

    // emit: p[c] = (sum_d cnt_d * e[d,c]) * g[m,c]
    float p[C];
#pragma unroll
    for (int c = 0; c < C; c++) p[c] = 0.0f;
#pragma unroll
    for (int d = 1; d < 12; d++) {           // bucket 0 (dist=-1) contributes 0
        const unsigned int cnt = (unsigned int)
            ((d < 6 ? (h0 >> (10 * d)) : (h1 >> (10 * (d - 6)))) & 1023u);
        const float fc = (float)cnt;
#pragma unroll
        for (int c = 0; c < C; c++)
            p[c] = fmaf(fc, er_s[d - 1][c], p[c]);
    }
    {
        const float4* gp = reinterpret_cast<const float4*>(g_node + (size_t)m * C);
        const float4 ga = gp[0];
        const float4 gb4 = gp[1];
        p[0] *= ga.x;  p[1] *= ga.y;  p[2] *= ga.z;  p[3] *= ga.w;
        p[4] *= gb4.x; p[5] *= gb4.y; p[6] *= gb4.z; p[7] *= gb4.w;
    }
#pragma unroll
    for (int off = 16; off; off >>= 1)
#pragma unroll
        for (int c = 0; c < C; c++)
            p[c] += __shfl_xor_sync(0xffffffffu, p[c], off);

    if (lane == 0) {
#pragma unroll
        for (int c = 0; c < C; c++) bp[wid][c] = p[c];
    }
    __syncthreads();
    if (threadIdx.x < C) {
        float s = 0.0f;
#pragma unroll
        for (int ww = 0; ww < 8; ww++) s += bp[ww][threadIdx.x];
        atomicAdd(out + gb * C + threadIdx.x, s);
    }
}

// ---------------------------------------------------------------------------
extern "C" void kernel_launch(void* const* d_in, const int* in_sizes, int n_in,
                              void* d_out, int out_size)
{
    const float* x    = (const float*)d_in[0];
    const float* dist = (const float*)d_in[1];
    const int*   bv   = (const int*)d_in[2];
    const float* fw1  = (const float*)d_in[3];
    const float* fb1  = (const float*)d_in[4];
    const float* fw2  = (const float*)d_in[5];
    const float* fb2  = (const float*)d_in[6];
    const float* rw1  = (const float*)d_in[7];
    const float* rb1  = (const float*)d_in[8];
    const float* rw2  = (const float*)d_in[9];
    const float* rb2  = (const float*)d_in[10];
    float* out = (float*)d_out;

    tgnan_k1<<<NN, FEAT>>>(x, bv, fw1, fb1, fw2, fb2, rw1, rb1, rw2, rb2, out);
    dim3 g2(8, MAXSEG, 1);                   // 8 m-groups x up to 128 segments
    tgnan_k2<<<g2, 256>>>(dist, out);
}